// round 5
// baseline (speedup 1.0000x reference)
#include <cuda_runtime.h>
#include <cuda_bf16.h>

// Problem constants (match reference)
#define HH   720
#define WW   1280
#define CC   2
#define NPIX (CC * HH * WW)        // 1,843,200
#define N4   (NPIX / 4)            // 460,800 float4 per frame
#define TEVT 10
#define TTOT 20

// One 1024-thread block per SM: co-residency guaranteed, occupancy 50%.
#define BLOCKS   148
#define TPB      1024
#define NTHREADS (BLOCKS * TPB)    // 151,552
// per-thread items: j=0..2 full (3*151552 = 454,656), j=3 partial:
#define NFULL    3
#define NPART    (N4 - NFULL * NTHREADS)   // 6,144 threads carry a 4th item

#define DECAY 0.9048374180359595f  // exp(-1/10) rounded to f32

// Persistent scratch (no cudaMalloc allowed)
__device__ float    g_buf[TEVT * NPIX];   // event count frames, ~73.7 MB
__device__ int      g_counts[TTOT];       // spike counts per step
__device__ float    g_bmin[BLOCKS];
__device__ float    g_bmax[BLOCKS];
__device__ unsigned g_barcnt = 0;         // barrier arrival counter
__device__ unsigned g_bargen = 0;         // barrier generation (monotonic forever)

// ---------------------------------------------------------------------------
// Device-wide sense-reversing barrier. Replay-safe: gen is monotonic across
// graph replays; count is reset by the last arriver BEFORE the gen bump.
// ---------------------------------------------------------------------------
__device__ __forceinline__ void grid_barrier() {
    __syncthreads();
    if (threadIdx.x == 0) {
        __threadfence();                                   // publish block's writes
        volatile unsigned* genp = &g_bargen;
        unsigned gen = *genp;                              // read BEFORE arriving
        unsigned v = atomicAdd(&g_barcnt, 1u);
        if (v == BLOCKS - 1) {
            atomicExch(&g_barcnt, 0u);                     // reset while others spin
            __threadfence();
            atomicAdd(&g_bargen, 1u);                      // release
        } else {
            while (*genp == gen) { __nanosleep(32); }
        }
        __threadfence();                                   // acquire others' writes
    }
    __syncthreads();
}

// ---------------------------------------------------------------------------
// One fused persistent kernel: init -> minmax -> scatter -> 20 LIF steps.
// Membrane state in registers (4 float4/thread); next frame prefetched
// across the per-step grid barrier.
// ---------------------------------------------------------------------------
__global__ void __launch_bounds__(TPB, 1) fused_kernel(
    const int* __restrict__ x, const int* __restrict__ y,
    const int* __restrict__ p, const float* __restrict__ t,
    float* __restrict__ out, int n)
{
    const int tid = blockIdx.x * TPB + threadIdx.x;
    __shared__ float smin[TPB / 32], smax[TPB / 32];
    __shared__ float s_tmin, s_tmax;
    __shared__ int   s_cnt, s_tot;

    // ===== Phase 1: zero buf, block-local min/max of t, zero counts =====
    {
        float4 z = make_float4(0.f, 0.f, 0.f, 0.f);
        float4* buf4 = reinterpret_cast<float4*>(g_buf);
        const int nb4 = TEVT * N4;
        for (int i = tid; i < nb4; i += NTHREADS) buf4[i] = z;
    }
    {
        float lmin = __int_as_float(0x7F800000), lmax = 0.0f;  // t in [0,1)
        for (int i = tid; i < n; i += NTHREADS) {
            float v = __ldcs(&t[i]);
            lmin = fminf(lmin, v);
            lmax = fmaxf(lmax, v);
        }
        #pragma unroll
        for (int off = 16; off > 0; off >>= 1) {
            lmin = fminf(lmin, __shfl_xor_sync(0xFFFFFFFFu, lmin, off));
            lmax = fmaxf(lmax, __shfl_xor_sync(0xFFFFFFFFu, lmax, off));
        }
        if ((threadIdx.x & 31) == 0) { smin[threadIdx.x >> 5] = lmin; smax[threadIdx.x >> 5] = lmax; }
        __syncthreads();
        if (threadIdx.x == 0) {
            float bm = smin[0], bM = smax[0];
            #pragma unroll
            for (int w = 1; w < TPB / 32; w++) { bm = fminf(bm, smin[w]); bM = fmaxf(bM, smax[w]); }
            g_bmin[blockIdx.x] = bm;
            g_bmax[blockIdx.x] = bM;
            if (blockIdx.x == 0) {
                #pragma unroll
                for (int k = 0; k < TTOT; k++) g_counts[k] = 0;
            }
        }
    }
    grid_barrier();

    // ===== Phase 2: reduce global min/max, scatter events =====
    {
        float m = __int_as_float(0x7F800000), M = 0.0f;
        if (threadIdx.x < BLOCKS) { m = g_bmin[threadIdx.x]; M = g_bmax[threadIdx.x]; }
        #pragma unroll
        for (int off = 16; off > 0; off >>= 1) {
            m = fminf(m, __shfl_xor_sync(0xFFFFFFFFu, m, off));
            M = fmaxf(M, __shfl_xor_sync(0xFFFFFFFFu, M, off));
        }
        if ((threadIdx.x & 31) == 0) { smin[threadIdx.x >> 5] = m; smax[threadIdx.x >> 5] = M; }
        __syncthreads();
        if (threadIdx.x == 0) {
            float bm = smin[0], bM = smax[0];
            #pragma unroll
            for (int w = 1; w < TPB / 32; w++) { bm = fminf(bm, smin[w]); bM = fmaxf(bM, smax[w]); }
            s_tmin = bm; s_tmax = bM;
        }
        __syncthreads();
    }
    {
        const float tmin = s_tmin, tmax = s_tmax;
        const bool  gt   = tmax > tmin;
        const float denom = gt ? (tmax - tmin) : 1.0f;
        for (int i = tid; i < n; i += NTHREADS) {
            float tv = __ldcs(&t[i]);
            float tn = gt ? ((tv - tmin) / denom * (10.0f - 1e-6f)) : 0.0f;
            int ti = (int)tn;                        // trunc toward zero, tn >= 0
            ti = min(max(ti, 0), TEVT - 1);
            int xi = min(max(__ldcs(&x[i]), 0), WW - 1);
            int yi = min(max(__ldcs(&y[i]), 0), HH - 1);
            int c  = min(max(__ldcs(&p[i]), 0), CC - 1);
            atomicAdd(&g_buf[((ti * CC + c) * HH + yi) * WW + xi], 1.0f);
        }
    }
    grid_barrier();   // scatter complete -> frames final

    // ===== Phase 3: 20 LIF steps, membrane in registers, frame prefetch =====
    float4 mreg[NFULL + 1];
    float4 fpre[NFULL + 1];
    #pragma unroll
    for (int j = 0; j <= NFULL; j++) {
        mreg[j] = make_float4(0.f, 0.f, 0.f, 0.f);
        fpre[j] = make_float4(0.f, 0.f, 0.f, 0.f);
    }
    const bool aP = (tid < NPART);     // 4th item active for first 6144 threads
    float thr = 1.0f;                  // identical recursion in every thread

    // preload frame 0
    {
        const float4* f4 = reinterpret_cast<const float4*>(g_buf);
        #pragma unroll
        for (int j = 0; j <= NFULL; j++) {
            const int idx = tid + j * NTHREADS;
            if ((j < NFULL) || aP) fpre[j] = __ldcs(&f4[idx]);
        }
    }

    for (int s = 0; s < TTOT; s++) {
        if (threadIdx.x == 0) s_cnt = 0;
        __syncthreads();

        float4* o4 = reinterpret_cast<float4*>(out + (size_t)s * NPIX);
        int cnt = 0;

        #pragma unroll
        for (int j = 0; j <= NFULL; j++) {
            const int  idx    = tid + j * NTHREADS;
            const bool active = (j < NFULL) || aP;
            if (active) {
                float4& m = mreg[j];
                float4  f = fpre[j];
                m.x = m.x * DECAY + f.x;
                m.y = m.y * DECAY + f.y;
                m.z = m.z * DECAY + f.z;
                m.w = m.w * DECAY + f.w;
                bool sx = (m.x >= thr), sy = (m.y >= thr);
                bool sz = (m.z >= thr), sw = (m.w >= thr);
                if (sx) { m.x -= thr; cnt++; }
                if (sy) { m.y -= thr; cnt++; }
                if (sz) { m.z -= thr; cnt++; }
                if (sw) { m.w -= thr; cnt++; }
                float4 o = make_float4(sx ? 1.f : 0.f, sy ? 1.f : 0.f,
                                       sz ? 1.f : 0.f, sw ? 1.f : 0.f);
                __stcs(&o4[idx], o);
            }
        }

        // prefetch next frame (independent of thr) BEFORE the barrier
        if (s + 1 < TEVT) {
            const float4* f4 = reinterpret_cast<const float4*>(g_buf + (size_t)(s + 1) * NPIX);
            #pragma unroll
            for (int j = 0; j <= NFULL; j++) {
                const int idx = tid + j * NTHREADS;
                if ((j < NFULL) || aP) fpre[j] = __ldcs(&f4[idx]);
            }
        } else {
            #pragma unroll
            for (int j = 0; j <= NFULL; j++) fpre[j] = make_float4(0.f, 0.f, 0.f, 0.f);
        }

        // block-reduce spike count -> one global atomic per block
        unsigned wsum = __reduce_add_sync(0xFFFFFFFFu, (unsigned)cnt);
        if ((threadIdx.x & 31) == 0) atomicAdd(&s_cnt, (int)wsum);
        __syncthreads();
        if (threadIdx.x == 0) atomicAdd(&g_counts[s], s_cnt);

        grid_barrier();                 // publishes & orders g_counts[s]

        if (threadIdx.x == 0) s_tot = g_counts[s];
        __syncthreads();
        float rate = (float)s_tot / (float)NPIX;
        thr = thr + 0.1f * (rate - 0.1f);
        thr = fminf(fmaxf(thr, 0.1f), 10.0f);
    }
}

// ---------------------------------------------------------------------------
// Launch: ONE graph node, allocation-free, graph-capturable.
// Inputs (metadata order): x:int32[4M], y:int32[4M], p:int32[4M], t:float32[4M]
// Output: float32[20*2*720*1280]
// ---------------------------------------------------------------------------
extern "C" void kernel_launch(void* const* d_in, const int* in_sizes, int n_in,
                              void* d_out, int out_size) {
    const int*   x = (const int*)d_in[0];
    const int*   y = (const int*)d_in[1];
    const int*   p = (const int*)d_in[2];
    const float* t = (const float*)d_in[3];
    float* out = (float*)d_out;
    int n = in_sizes[0];

    fused_kernel<<<BLOCKS, TPB>>>(x, y, p, t, out, n);
}

// round 6
// speedup vs baseline: 1.5520x; 1.5520x over previous
#include <cuda_runtime.h>
#include <cuda_bf16.h>

// Problem constants (match reference)
#define HH   720
#define WW   1280
#define CC   2
#define NPIX   (CC * HH * WW)      // 1,843,200
#define NPIX16 (NPIX / 16)         // 115,200 uint4-of-bytes per frame
#define TEVT 10
#define TTOT 20

// One 1024-thread block per SM: co-residency guaranteed.
#define BLOCKS   148
#define TPB      1024
#define NTHREADS (BLOCKS * TPB)    // 151,552 (first 115,200 own pixels)

#define DECAY 0.9048374180359595f  // exp(-1/10) rounded to f32

// Persistent scratch (no cudaMalloc allowed)
__device__ unsigned           g_buf32[TEVT * NPIX / 4];  // uint8 counts, 18.4 MB
__device__ unsigned long long g_pack[TTOT];              // (arrivals<<32)|count
__device__ float              g_bmin[BLOCKS];
__device__ float              g_bmax[BLOCKS];
__device__ unsigned           g_barcnt = 0;              // phase barrier counter
__device__ unsigned           g_bargen = 0;              // monotonic generation

// ---------------------------------------------------------------------------
// Device-wide barrier (used only twice: after init+minmax, after scatter).
// Replay-safe: gen is monotonic forever; count reset by last arriver.
// ---------------------------------------------------------------------------
__device__ __forceinline__ void grid_barrier() {
    __syncthreads();
    if (threadIdx.x == 0) {
        __threadfence();
        volatile unsigned* genp = &g_bargen;
        unsigned gen = *genp;
        unsigned v = atomicAdd(&g_barcnt, 1u);
        if (v == BLOCKS - 1) {
            atomicExch(&g_barcnt, 0u);
            __threadfence();
            atomicAdd(&g_bargen, 1u);
        } else {
            while (*genp == gen) { __nanosleep(32); }
        }
        __threadfence();
    }
    __syncthreads();
}

// ---------------------------------------------------------------------------
// Fused persistent kernel: init -> minmax -> scatter -> 20 LIF steps.
// Membrane in registers (16 f32/thread); per-step sync is ONE packed atomic
// per block (no fences, no store drains).
// ---------------------------------------------------------------------------
__global__ void __launch_bounds__(TPB, 1) fused_kernel(
    const int* __restrict__ x, const int* __restrict__ y,
    const int* __restrict__ p, const float* __restrict__ t,
    float* __restrict__ out, int n)
{
    const int tid = blockIdx.x * TPB + threadIdx.x;
    __shared__ float smin[TPB / 32], smax[TPB / 32];
    __shared__ float s_tmin, s_tmax;
    __shared__ int   s_cnt, s_tot;

    // ===== Phase 1: zero buf + pack, block-local min/max of t =====
    {
        uint4 z = make_uint4(0u, 0u, 0u, 0u);
        uint4* b16 = reinterpret_cast<uint4*>(g_buf32);
        const int nb = TEVT * NPIX16;                // 1,152,000 uint4
        for (int i = tid; i < nb; i += NTHREADS) b16[i] = z;
        if (tid == 0) {
            #pragma unroll
            for (int k = 0; k < TTOT; k++) g_pack[k] = 0ull;
        }
    }
    {
        float lmin = __int_as_float(0x7F800000), lmax = 0.0f;  // t in [0,1)
        const float4* t4 = reinterpret_cast<const float4*>(t);
        const int n4 = n >> 2;
        for (int i = tid; i < n4; i += NTHREADS) {
            float4 v = __ldcs(&t4[i]);
            lmin = fminf(fminf(lmin, v.x), fminf(v.y, fminf(v.z, v.w)));
            lmax = fmaxf(fmaxf(lmax, v.x), fmaxf(v.y, fmaxf(v.z, v.w)));
        }
        for (int i = (n4 << 2) + tid; i < n; i += NTHREADS) {   // tail (none for 4M)
            float v = t[i];
            lmin = fminf(lmin, v); lmax = fmaxf(lmax, v);
        }
        #pragma unroll
        for (int off = 16; off > 0; off >>= 1) {
            lmin = fminf(lmin, __shfl_xor_sync(0xFFFFFFFFu, lmin, off));
            lmax = fmaxf(lmax, __shfl_xor_sync(0xFFFFFFFFu, lmax, off));
        }
        if ((threadIdx.x & 31) == 0) { smin[threadIdx.x >> 5] = lmin; smax[threadIdx.x >> 5] = lmax; }
        __syncthreads();
        if (threadIdx.x == 0) {
            float bm = smin[0], bM = smax[0];
            #pragma unroll
            for (int w = 1; w < TPB / 32; w++) { bm = fminf(bm, smin[w]); bM = fmaxf(bM, smax[w]); }
            g_bmin[blockIdx.x] = bm;
            g_bmax[blockIdx.x] = bM;
        }
    }
    grid_barrier();

    // ===== Phase 2: global min/max, scatter events (byte-packed atomics) =====
    {
        float m = __int_as_float(0x7F800000), M = 0.0f;
        if (threadIdx.x < BLOCKS) { m = g_bmin[threadIdx.x]; M = g_bmax[threadIdx.x]; }
        #pragma unroll
        for (int off = 16; off > 0; off >>= 1) {
            m = fminf(m, __shfl_xor_sync(0xFFFFFFFFu, m, off));
            M = fmaxf(M, __shfl_xor_sync(0xFFFFFFFFu, M, off));
        }
        if ((threadIdx.x & 31) == 0) { smin[threadIdx.x >> 5] = m; smax[threadIdx.x >> 5] = M; }
        __syncthreads();
        if (threadIdx.x == 0) {
            float bm = smin[0], bM = smax[0];
            #pragma unroll
            for (int w = 1; w < TPB / 32; w++) { bm = fminf(bm, smin[w]); bM = fmaxf(bM, smax[w]); }
            s_tmin = bm; s_tmax = bM;
        }
        __syncthreads();
    }
    {
        const float tmin = s_tmin, tmax = s_tmax;
        const bool  gt   = tmax > tmin;
        const float denom = gt ? (tmax - tmin) : 1.0f;
        const int4*   x4 = reinterpret_cast<const int4*>(x);
        const int4*   y4 = reinterpret_cast<const int4*>(y);
        const int4*   p4 = reinterpret_cast<const int4*>(p);
        const float4* t4 = reinterpret_cast<const float4*>(t);
        const int n4 = n >> 2;
        for (int i = tid; i < n4; i += NTHREADS) {
            int4   xv = __ldcs(&x4[i]);
            int4   yv = __ldcs(&y4[i]);
            int4   pv = __ldcs(&p4[i]);
            float4 tv = __ldcs(&t4[i]);
            #pragma unroll
            for (int e = 0; e < 4; e++) {
                float te = (e == 0) ? tv.x : (e == 1) ? tv.y : (e == 2) ? tv.z : tv.w;
                int   xe = (e == 0) ? xv.x : (e == 1) ? xv.y : (e == 2) ? xv.z : xv.w;
                int   ye = (e == 0) ? yv.x : (e == 1) ? yv.y : (e == 2) ? yv.z : yv.w;
                int   pe = (e == 0) ? pv.x : (e == 1) ? pv.y : (e == 2) ? pv.z : pv.w;
                float tn = gt ? ((te - tmin) / denom * (10.0f - 1e-6f)) : 0.0f;
                int ti = (int)tn;                          // trunc, tn >= 0
                ti = min(max(ti, 0), TEVT - 1);
                int xi = min(max(xe, 0), WW - 1);
                int yi = min(max(ye, 0), HH - 1);
                int c  = min(max(pe, 0), CC - 1);
                int addr = ((ti * CC + c) * HH + yi) * WW + xi;   // byte index
                atomicAdd(&g_buf32[addr >> 2], 1u << ((addr & 3) * 8));
            }
        }
        // scalar tail (n % 4 == 0 for this problem; kept for safety)
        for (int i = (n4 << 2) + tid; i < n; i += NTHREADS) {
            float tn = gt ? ((t[i] - tmin) / denom * (10.0f - 1e-6f)) : 0.0f;
            int ti = min(max((int)tn, 0), TEVT - 1);
            int xi = min(max(x[i], 0), WW - 1);
            int yi = min(max(y[i], 0), HH - 1);
            int c  = min(max(p[i], 0), CC - 1);
            int addr = ((ti * CC + c) * HH + yi) * WW + xi;
            atomicAdd(&g_buf32[addr >> 2], 1u << ((addr & 3) * 8));
        }
    }
    grid_barrier();   // scatter complete -> frames final

    // ===== Phase 3: 20 LIF steps. 16 pixels/thread, fence-free count sync. =====
    const bool active = (tid < NPIX16);   // warp-aligned: 115,200 % 32 == 0
    float mreg[16];
    #pragma unroll
    for (int k = 0; k < 16; k++) mreg[k] = 0.0f;
    uint4 fpre = make_uint4(0u, 0u, 0u, 0u);
    float thr = 1.0f;

    if (active) {   // preload frame 0 (16 packed uint8 counts)
        fpre = __ldcs(reinterpret_cast<const uint4*>(g_buf32) + tid);
    }

    for (int s = 0; s < TTOT; s++) {
        if (threadIdx.x == 0) s_cnt = 0;
        __syncthreads();

        int cnt = 0;
        if (active) {
            float4* o4 = reinterpret_cast<float4*>(out + (size_t)s * NPIX) + tid * 4;
            const unsigned w[4] = { fpre.x, fpre.y, fpre.z, fpre.w };
            #pragma unroll
            for (int q = 0; q < 4; q++) {
                float4 o;
                float* ov = &o.x;
                #pragma unroll
                for (int b = 0; b < 4; b++) {
                    int k = q * 4 + b;
                    float f = (float)((w[q] >> (8 * b)) & 0xFFu);
                    float m = mreg[k] * DECAY + f;
                    bool sp = (m >= thr);
                    if (sp) { m -= thr; cnt++; }
                    mreg[k] = m;
                    ov[b] = sp ? 1.0f : 0.0f;
                }
                __stcs(&o4[q], o);
            }
            // prefetch next frame (no dependence on thr_{s+1})
            if (s + 1 < TEVT) {
                fpre = __ldcs(reinterpret_cast<const uint4*>(g_buf32)
                              + (size_t)(s + 1) * NPIX16 + tid);
            } else {
                fpre = make_uint4(0u, 0u, 0u, 0u);
            }
        }

        // block-reduce spike count
        unsigned wsum = __reduce_add_sync(0xFFFFFFFFu, (unsigned)cnt);
        if ((threadIdx.x & 31) == 0) atomicAdd(&s_cnt, (int)wsum);
        __syncthreads();

        // ONE packed atomic = reduction + barrier; no fences, no store drain.
        if (threadIdx.x == 0) {
            unsigned long long add = (1ull << 32) | (unsigned)s_cnt;
            unsigned long long v = atomicAdd(&g_pack[s], add) + add;
            while ((v >> 32) < (unsigned)BLOCKS) {
                __nanosleep(64);
                v = *(volatile unsigned long long*)&g_pack[s];
            }
            s_tot = (int)(unsigned)v;      // low 32 bits: global spike count
        }
        __syncthreads();

        float rate = (float)s_tot / (float)NPIX;
        thr = thr + 0.1f * (rate - 0.1f);
        thr = fminf(fmaxf(thr, 0.1f), 10.0f);
    }
}

// ---------------------------------------------------------------------------
// Launch: ONE graph node, allocation-free, graph-capturable.
// Inputs (metadata order): x:int32[4M], y:int32[4M], p:int32[4M], t:float32[4M]
// Output: float32[20*2*720*1280]
// ---------------------------------------------------------------------------
extern "C" void kernel_launch(void* const* d_in, const int* in_sizes, int n_in,
                              void* d_out, int out_size) {
    const int*   x = (const int*)d_in[0];
    const int*   y = (const int*)d_in[1];
    const int*   p = (const int*)d_in[2];
    const float* t = (const float*)d_in[3];
    float* out = (float*)d_out;
    int n = in_sizes[0];

    fused_kernel<<<BLOCKS, TPB>>>(x, y, p, t, out, n);
}